// round 16
// baseline (speedup 1.0000x reference)
#include <cuda_runtime.h>
#include <math.h>

// ---------------- problem constants ----------------
#define BSZ 256
#define NT  4096        // BSZ*T images
#define PT  256
#define ALPHA_C 0.5f

#define XR_SZ   (NT*1024)
#define MU_OFF  XR_SZ
#define MU_SZ   (BSZ*PT)
#define COV_OFF (MU_OFF+MU_SZ)
#define COV_SZ  (BSZ*PT*PT)
#define PM_OFF  (COV_OFF+COV_SZ)

// ---------------- scratch ----------------
__device__ float g_h1[NT*32*16*16];
__device__ float g_h2[NT*32*8*8];
__device__ float g_h3[NT*64*4*4];
__device__ float g_h4[NT*64*2*2];
__device__ float g_h5[NT*64];
__device__ float g_Dv[BSZ*4096];
__device__ float g_Bv[BSZ*3840];
__device__ float g_z [BSZ*PT];
__device__ float g_hd[BSZ*1024];
__device__ float g_d1[NT*64*2*2];
__device__ float g_d2[NT*64*4*4];
__device__ float g_d3[NT*32*8*8];
__device__ float g_d4[NT*32*16*16];
__device__ float g_wp4[64*64*9];
__device__ float g_wp3[64*32*9];
__device__ float g_wp2[32*32*9];
__device__ float g_w5p[64*256];     // enc5 GEMM weights  [co][ci*4+iy*2+ix]
__device__ float g_wp5g[256*64];    // dec1 GEMM weights  [co*4+y*2+x][ci]
__device__ float g_bt5e[256];       // dec1 expanded bias

// =================================================================
// enc1 dedicated kernel: Conv(1->32, k3,s2,p1)+ReLU, 4 images/CTA.
// =================================================================
__global__ void __launch_bounds__(256)
enc1_conv(const float* __restrict__ x, const float* __restrict__ w,
          const float* __restrict__ bias, float* __restrict__ out) {
    int n0 = blockIdx.x * 4;
    __shared__ float si[4*1024];
    __shared__ float sw[288];
    __shared__ float sb[32];
    {
        const float4* gp = (const float4*)(x + (size_t)n0 * 1024);
        float4* sp = (float4*)si;
        #pragma unroll
        for (int l = 0; l < 4; l++) sp[threadIdx.x + l*256] = gp[threadIdx.x + l*256];
        for (int e = threadIdx.x; e < 288; e += 256) sw[e] = w[e];
        if (threadIdx.x < 32)  sb[threadIdx.x] = bias[threadIdx.x];
    }
    __syncthreads();
    int p = threadIdx.x;
    int y = p >> 4, xc = p & 15;

    float in9[4][9];
    #pragma unroll
    for (int q = 0; q < 4; q++) {
        #pragma unroll
        for (int ky = 0; ky < 3; ky++) {
            int iy = 2*y + ky - 1;
            #pragma unroll
            for (int kx = 0; kx < 3; kx++) {
                int ix = 2*xc + kx - 1;
                in9[q][ky*3+kx] = ((unsigned)iy < 32u && (unsigned)ix < 32u)
                                  ? si[q*1024 + iy*32 + ix] : 0.f;
            }
        }
    }
    for (int c = 0; c < 32; c++) {
        float wv[9];
        #pragma unroll
        for (int k = 0; k < 9; k++) wv[k] = sw[c*9 + k];
        float bb = sb[c];
        #pragma unroll
        for (int q = 0; q < 4; q++) {
            float s = bb;
            #pragma unroll
            for (int k = 0; k < 9; k++) s += in9[q][k] * wv[k];
            out[(size_t)(n0 + q)*8192 + c*256 + p] = fmaxf(s, 0.f);
        }
    }
}

// =================================================================
// Encoder conv (k3,s2,p1) + ReLU as implicit GEMM.
// B-tile staging offsets hoisted out of the channel loop (invariant).
// Requires (9*CB*BN) % THR == 0.
// =================================================================
template<int CIN,int HIN,int COUT,int CB,int BM,int BN,int TM,int TNW>
__global__ void __launch_bounds__((BM/TM)*(BN/TNW), 2)
enc_conv(const float* __restrict__ in, const float* __restrict__ w,
         const float* __restrict__ bias, float* __restrict__ out) {
    const int THR = (BM/TM)*(BN/TNW);
    const int H  = HIN/2;
    const int H2 = H*H;
    const int BK = 9*CB;
    const int SELT = (BK*BN)/THR;
    __shared__ float As[BK][BM];
    __shared__ float Bs[BK][BN+4];
    const int tid = threadIdx.x;
    const int px0 = blockIdx.x * BN;
    const int MT  = BM/TM;
    const int tidm = tid % MT, tidn = tid / MT;

    // hoisted B-tile gmem offsets (c0 = 0 base; -1 = padding)
    int boff[SELT];
    #pragma unroll
    for (int s = 0; s < SELT; s++) {
        int e = tid + s*THR;
        int k = e / BN, col = e % BN;
        int cl = k / 9, tap = k - 9*cl;
        int ky = tap/3, kx = tap - 3*(tap/3);
        int px = px0 + col;
        int n   = px / H2;
        int rem = px - n*H2;
        int y = rem / H, x = rem - (rem/H)*H;
        int iy = 2*y + ky - 1, ix = 2*x + kx - 1;
        bool ok = ((unsigned)iy < (unsigned)HIN) && ((unsigned)ix < (unsigned)HIN);
        boff[s] = ok ? (((n*CIN + cl)*HIN + iy)*HIN + ix) : -1;
    }

    float acc[TM][TNW] = {};
    int coff = 0;                       // c0 * HIN * HIN

    for (int c0 = 0; c0 < CIN; c0 += CB, coff += CB*HIN*HIN) {
        for (int e = tid; e < BK*BM; e += THR) {
            int k = e / BM, co = e % BM;
            int cl = k / 9, tap = k - 9*cl;
            As[k][co] = w[(co*CIN + c0 + cl)*9 + tap];
        }
        #pragma unroll
        for (int s = 0; s < SELT; s++) {
            int e = tid + s*THR;
            int k = e / BN, col = e % BN;
            float v = 0.f;
            if (boff[s] >= 0) v = in[(size_t)boff[s] + coff];
            Bs[k][col] = v;
        }
        __syncthreads();
        #pragma unroll
        for (int k = 0; k < BK; k++) {
            float a[TM], b[TNW];
            #pragma unroll
            for (int r = 0; r < TM; r++) a[r] = As[k][tidm*TM + r];
            #pragma unroll
            for (int c = 0; c < TNW; c++) b[c] = Bs[k][tidn*TNW + c];
            #pragma unroll
            for (int r = 0; r < TM; r++)
                #pragma unroll
                for (int c = 0; c < TNW; c++)
                    acc[r][c] += a[r] * b[c];
        }
        __syncthreads();
    }
    #pragma unroll
    for (int r = 0; r < TM; r++) {
        int co = tidm*TM + r;
        float bb = bias[co];
        #pragma unroll
        for (int c = 0; c < TNW; c++) {
            int px = px0 + tidn*TNW + c;
            int n = px / H2, rem = px - (px/H2)*H2;
            out[((size_t)n*COUT + co)*H2 + rem] = fmaxf(acc[r][c] + bb, 0.f);
        }
    }
}

// =================================================================
// Weight packing
// =================================================================
__device__ __forceinline__ void pack_one(const float* __restrict__ w,
                                         float* __restrict__ wp,
                                         int CIN, int COUT, int idx) {
    int kx = idx % 3; int r = idx / 3;
    int ky = r % 3;   r /= 3;
    int co = r % COUT; int ci = r / COUT;
    int py = (ky != 1), px = (kx != 1);
    int p = py*2 + px;
    int ty = (ky == 2) ? 1 : 0;
    int tx = (kx == 2) ? 1 : 0;
    int ntx = px ? 2 : 1;
    int ntaps = (py ? 2 : 1) * ntx;
    int K = CIN * ntaps;
    const int cum[4] = {0, 1, 3, 5};
    int off = COUT*CIN*cum[p];
    wp[off + co*K + ci*ntaps + ty*ntx + tx] = w[((ci*COUT + co)*3 + ky)*3 + kx];
}

__global__ void pack_all(const float* __restrict__ wt4, const float* __restrict__ wt3,
                         const float* __restrict__ wt2,
                         const float* __restrict__ w5, const float* __restrict__ wt5,
                         const float* __restrict__ bt5,
                         float* wp4, float* wp3, float* wp2,
                         float* w5p, float* wp5g, float* bt5e) {
    int idx = blockIdx.x * blockDim.x + threadIdx.x;
    if      (idx < 36864)  pack_one(wt4, wp4, 64, 64, idx);
    else if (idx < 55296)  pack_one(wt3, wp3, 64, 32, idx - 36864);
    else if (idx < 64512)  pack_one(wt2, wp2, 32, 32, idx - 55296);
    else if (idx < 80896) {
        int e = idx - 64512;
        int ix = e & 1, iy = (e >> 1) & 1, ci = (e >> 2) & 63, co = e >> 8;
        w5p[co*256 + ci*4 + iy*2 + ix] = w5[((co*64 + ci)*3 + iy+1)*3 + ix+1];
    }
    else if (idx < 97280) {
        int e = idx - 80896;
        int ci = e & 63, yx = (e >> 6) & 3, co = e >> 8;
        int y = yx >> 1, x = yx & 1;
        wp5g[(co*4 + yx)*64 + ci] = wt5[((ci*64 + co)*3 + y+1)*3 + x+1];
    }
    else if (idx < 97536) {
        int e = idx - 97280;
        bt5e[e] = bt5[e >> 2];
    }
}

// =================================================================
// Decoder transposed conv (parity decomposition), implicit GEMM.
// B-tile staging offsets hoisted out of the k0 loop (invariant geometry;
// channel index advances by BK>>sh per iteration). Requires (16*BN)%THR==0.
// =================================================================
template<int CIN,int HI,int COUT,int BM,int BN,int TM,int TNW,int ACT>
__global__ void __launch_bounds__((BM/TM)*(BN/TNW), 2)
dec_convt(const float* __restrict__ in, const float* __restrict__ wp,
          const float* __restrict__ bias, float* __restrict__ out) {
    const int THR = (BM/TM)*(BN/TNW);
    const int HO  = 2*HI;
    const int HI2 = HI*HI;
    const int BK = 16;
    const int SELT = (BK*BN)/THR;
    __shared__ float As[BK][BM];
    __shared__ float Bs[BK][BN+4];
    const int tid = threadIdx.x;
    const int par = blockIdx.y;
    const int py = par >> 1, pxp = par & 1;
    const int sh = py + pxp;
    const int ntaps = 1 << sh;
    const int ntxm1 = pxp;
    const int K = CIN << sh;
    const int cum[4] = {0, 1, 3, 5};
    const float* wq = wp + (size_t)COUT*CIN*cum[par];

    const int pxl0 = blockIdx.x * BN;
    const int MT = BM/TM;
    const int tidm = tid % MT, tidn = tid / MT;

    // hoisted B-tile gmem offsets (k0 = 0 base; -1 = out of range)
    // per k0 step, channel advances by BK>>sh -> offset stride (BK>>sh)*HI*HI
    int boff[SELT];
    #pragma unroll
    for (int s = 0; s < SELT; s++) {
        int e = tid + s*THR;
        int kk = e / BN, col = e % BN;
        int ci = kk >> sh;                 // k0=0 part
        int t  = kk & (ntaps - 1);
        int ty = t >> pxp;
        int tx = t & ntxm1;
        int dy = (py && ty == 0) ? 1 : 0;
        int dx = (pxp && tx == 0) ? 1 : 0;
        int pxl = pxl0 + col;
        int n   = pxl / HI2;
        int rem = pxl - n*HI2;
        int yi = rem / HI, xi = rem - (rem/HI)*HI;
        int iy = yi + dy, ix = xi + dx;
        bool ok = (iy < HI) && (ix < HI);
        boff[s] = ok ? (((n*CIN + ci)*HI + iy)*HI + ix) : -1;
    }
    const int kstride = (BK >> sh) * HI2;  // offset advance per k0 step

    float acc[TM][TNW] = {};
    int koff = 0;

    for (int k0 = 0; k0 < K; k0 += BK, koff += kstride) {
        for (int e = tid; e < BK*BM; e += THR) {
            int k = e / BM, co = e % BM;
            As[k][co] = wq[co*K + k0 + k];
        }
        #pragma unroll
        for (int s = 0; s < SELT; s++) {
            int e = tid + s*THR;
            int kk = e / BN, col = e % BN;
            float v = 0.f;
            if (boff[s] >= 0) v = in[(size_t)boff[s] + koff];
            Bs[kk][col] = v;
        }
        __syncthreads();
        #pragma unroll
        for (int k = 0; k < BK; k++) {
            float a[TM], b[TNW];
            #pragma unroll
            for (int r = 0; r < TM; r++) a[r] = As[k][tidm*TM + r];
            #pragma unroll
            for (int c = 0; c < TNW; c++) b[c] = Bs[k][tidn*TNW + c];
            #pragma unroll
            for (int r = 0; r < TM; r++)
                #pragma unroll
                for (int c = 0; c < TNW; c++)
                    acc[r][c] += a[r] * b[c];
        }
        __syncthreads();
    }
    #pragma unroll
    for (int r = 0; r < TM; r++) {
        int co = tidm*TM + r;
        float bb = bias[co];
        #pragma unroll
        for (int c = 0; c < TNW; c++) {
            int pxl = pxl0 + tidn*TNW + c;
            int n   = pxl / HI2;
            int rem = pxl - n*HI2;
            int yi = rem / HI, xi = rem - (rem/HI)*HI;
            float s = acc[r][c] + bb;
            float o;
            if (ACT) o = 1.f / (1.f + expf(-s));
            else     o = (s > 0.f) ? s : expm1f(s);
            out[(((size_t)n*COUT + co)*HO + 2*yi + py)*HO + 2*xi + pxp] = o;
        }
    }
}

// =================================================================
// Final decoder layer (Cout=1) + sigmoid: one CTA per image.
// =================================================================
__global__ void __launch_bounds__(256)
dec_final(const float* __restrict__ in, const float* __restrict__ w,
          const float* __restrict__ bias, float* __restrict__ out) {
    int n = blockIdx.x;
    __shared__ float si[32*256];
    __shared__ float sw[288];
    const float4* gp = (const float4*)(in + (size_t)n * 8192);
    float4* sp = (float4*)si;
    for (int e = threadIdx.x; e < 2048; e += 256) sp[e] = gp[e];
    for (int e = threadIdx.x; e < 288; e += 256)  sw[e] = w[e];
    __syncthreads();
    float b0 = bias[0];
    #pragma unroll
    for (int p = 0; p < 4; p++) {
        int px = threadIdx.x + p*256;
        int y = px >> 5, x = px & 31;
        float s = b0;
        #pragma unroll
        for (int ky = 0; ky < 3; ky++) {
            int ty = y + 1 - ky;
            if (ty < 0 || (ty & 1)) continue;
            int iy = ty >> 1;
            if (iy >= 16) continue;
            #pragma unroll
            for (int kx = 0; kx < 3; kx++) {
                int tx = x + 1 - kx;
                if (tx < 0 || (tx & 1)) continue;
                int ix = tx >> 1;
                if (ix >= 16) continue;
                const float* sic = si + iy*16 + ix;
                const float* swc = sw + ky*3 + kx;
                #pragma unroll 8
                for (int ci = 0; ci < 32; ci++)
                    s += sic[ci*256] * swc[ci*9];
            }
        }
        out[(size_t)n*1024 + px] = 1.f / (1.f + expf(-s));
    }
}

// =================================================================
// Merged FC-heads GEMM, 8x8 microtile, float4 staging.
// =================================================================
__global__ void __launch_bounds__(256)
gemm_heads(const float* __restrict__ A,
           const float* __restrict__ wD, const float* __restrict__ bD, float* __restrict__ oD,
           const float* __restrict__ wB, const float* __restrict__ bB, float* __restrict__ oB,
           const float* __restrict__ wM, const float* __restrict__ bM, float* __restrict__ oM) {
    const int K = 1024;
    __shared__ float As[16][132];
    __shared__ float Bs[16][132];
    int tid = threadIdx.x;
    int tidm = tid & 15, tidn = tid >> 4;
    int m0 = blockIdx.y * 128;
    int ng = blockIdx.x * 128;

    const float* W; const float* bias; float* C; int Nld; int n0;
    if (ng < 4096)      { W = wD; bias = bD; C = oD; Nld = 4096; n0 = ng; }
    else if (ng < 7936) { W = wB; bias = bB; C = oB; Nld = 3840; n0 = ng - 4096; }
    else                { W = wM; bias = bM; C = oM; Nld = 256;  n0 = ng - 7936; }

    float acc[8][8] = {};
    for (int k0 = 0; k0 < K; k0 += 16) {
        #pragma unroll
        for (int l = 0; l < 2; l++) {
            int q = tid + l*256;
            int row = q >> 2, kq = q & 3;
            float4 v = *(const float4*)&A[(size_t)(m0 + row)*K + k0 + kq*4];
            As[kq*4+0][row] = v.x; As[kq*4+1][row] = v.y;
            As[kq*4+2][row] = v.z; As[kq*4+3][row] = v.w;
        }
        #pragma unroll
        for (int l = 0; l < 2; l++) {
            int q = tid + l*256;
            int row = q >> 2, kq = q & 3;
            float4 v = *(const float4*)&W[(size_t)(n0 + row)*K + k0 + kq*4];
            Bs[kq*4+0][row] = v.x; Bs[kq*4+1][row] = v.y;
            Bs[kq*4+2][row] = v.z; Bs[kq*4+3][row] = v.w;
        }
        __syncthreads();
        #pragma unroll
        for (int k = 0; k < 16; k++) {
            float a[8], b[8];
            #pragma unroll
            for (int r = 0; r < 8; r++) a[r] = As[k][tidm*8 + r];
            #pragma unroll
            for (int c = 0; c < 8; c++) b[c] = Bs[k][tidn*8 + c];
            #pragma unroll
            for (int r = 0; r < 8; r++)
                #pragma unroll
                for (int c = 0; c < 8; c++)
                    acc[r][c] += a[r] * b[c];
        }
        __syncthreads();
    }
    #pragma unroll
    for (int r = 0; r < 8; r++) {
        int m = m0 + tidm*8 + r;
        #pragma unroll
        for (int c = 0; c < 8; c++) {
            int n = n0 + tidn*8 + c;
            C[(size_t)m*Nld + n] = acc[r][c] + bias[n];
        }
    }
}

// ---------------- generic GEMM + activation: C = A@B^T + bias ----------------
template<int ACT>
__global__ void gemm_bt64(const float* __restrict__ A, const float* __restrict__ Bm,
                          const float* __restrict__ bias, float* __restrict__ C,
                          int M, int N, int K) {
    __shared__ float As[64][17];
    __shared__ float Bs[64][17];
    int tid = threadIdx.x;
    int tx = tid & 15, ty = tid >> 4;
    int m0 = blockIdx.y * 64, n0 = blockIdx.x * 64;

    float acc[4][4] = {};
    for (int k0 = 0; k0 < K; k0 += 16) {
        #pragma unroll
        for (int l = 0; l < 4; l++) {
            int e = tid + l * 256;
            int mm = e >> 4, kk = e & 15;
            As[mm][kk] = A[(size_t)(m0 + mm) * K + k0 + kk];
            Bs[mm][kk] = Bm[(size_t)(n0 + mm) * K + k0 + kk];
        }
        __syncthreads();
        #pragma unroll
        for (int k = 0; k < 16; k++) {
            float a[4], b[4];
            #pragma unroll
            for (int r = 0; r < 4; r++) a[r] = As[ty*4 + r][k];
            #pragma unroll
            for (int c = 0; c < 4; c++) b[c] = Bs[tx*4 + c][k];
            #pragma unroll
            for (int r = 0; r < 4; r++)
                #pragma unroll
                for (int c = 0; c < 4; c++)
                    acc[r][c] += a[r] * b[c];
        }
        __syncthreads();
    }
    #pragma unroll
    for (int r = 0; r < 4; r++)
        #pragma unroll
        for (int c = 0; c < 4; c++) {
            float v = acc[r][c] + bias[n0 + tx*4 + c];
            if (ACT == 1) v = fmaxf(v, 0.f);
            if (ACT == 2) v = (v > 0.f) ? v : expm1f(v);
            C[(size_t)(m0 + ty*4 + r) * N + n0 + tx*4 + c] = v;
        }
}

// ---------------- Pm builder — float4 stores ----------------
__global__ void build_pm4(const float* __restrict__ Dv, const float* __restrict__ Bv,
                          float4* __restrict__ Pm) {
    size_t idx = (size_t)blockIdx.x * blockDim.x + threadIdx.x;
    size_t total = (size_t)BSZ * PT * 64;
    if (idx >= total) return;
    int c4 = idx & 63;
    int r  = (idx >> 6) & 255;
    int b  = idx >> 14;
    int t = r >> 4, i = r & 15;
    int s = c4 >> 2, j0 = (c4 & 3) * 4;
    float4 v = {0.f, 0.f, 0.f, 0.f};
    if (t == s) {
        v = *(const float4*)(Dv + b*4096 + t*256 + i*16 + j0);
        if (i >= j0 && i < j0+4) { (&v.x)[i - j0] += ALPHA_C; }
    } else if (t == s + 1) {
        v = *(const float4*)(Bv + b*3840 + s*256 + i*16 + j0);
    } else if (s == t + 1) {
        const float* bp = Bv + b*3840 + t*256 + i;
        v.x = bp[(j0+0)*16]; v.y = bp[(j0+1)*16];
        v.z = bp[(j0+2)*16]; v.w = bp[(j0+3)*16];
    }
    Pm[idx] = v;
}

// ---------------- block-tridiagonal Cholesky + L^{-1} + z ----------------
__global__ void chol_cov_z(const float* __restrict__ Dv, const float* __restrict__ Bv,
                           const float* __restrict__ mu, const float* __restrict__ eps,
                           float* __restrict__ cov, float* __restrict__ z) {
    int b = blockIdx.x;
    int tid = threadIdx.x;
    int i = tid >> 4, j = tid & 15;

    __shared__ float A[16][16];
    __shared__ float Linv[16][16];
    __shared__ float LinvP[16][16];
    __shared__ float Mb[16][16];
    __shared__ float W[16][16];
    __shared__ float rowbuf[2][16*256];
    __shared__ float epss[256];

    epss[tid] = eps[b*256 + tid];

    float* prev = rowbuf[0];
    float* cur  = rowbuf[1];

    for (int t = 0; t < 16; t++) {
        const float* Dp = Dv + b*4096 + t*256;
        float a = 0.5f * (Dp[i*16 + j] + Dp[j*16 + i]);   // symmetrize_input=True
        if (i == j) a += ALPHA_C;
        __syncthreads();
        A[i][j] = a;
        __syncthreads();

        if (t > 0) {
            const float* Bp = Bv + b*3840 + (t-1)*256;
            float s = 0.f;
            #pragma unroll
            for (int k = 0; k < 16; k++) s += Bp[i*16 + k] * LinvP[j][k];
            Mb[i][j] = s;
            __syncthreads();
            float u = 0.f;
            #pragma unroll
            for (int k = 0; k < 16; k++) u += Mb[i][k] * Mb[j][k];
            A[i][j] -= u;
            __syncthreads();
        }

        // Cholesky: 2 barriers per column
        for (int k = 0; k < 16; k++) {
            float aik = A[i][k], ajk = A[j][k], akk = A[k][k];
            __syncthreads();
            if (j == k && i >= k)      A[i][k] = aik * rsqrtf(akk);
            else if (j > k && j <= i)  A[i][j] -= aik * ajk / akk;
            __syncthreads();
        }

        // Linv = A_lower^{-1} : 16 threads, fully unrolled
        if (tid < 16) {
            int c = tid;
            float x[16];
            #pragma unroll
            for (int r = 0; r < 16; r++) {
                float s = 0.f;
                #pragma unroll
                for (int k = 0; k < 16; k++)
                    if (k < r) s += A[r][k] * x[k];
                float v;
                if (r == c)      v = 1.f / A[r][r];
                else if (r < c)  v = 0.f;
                else             v = -s / A[r][r];
                x[r] = v;
            }
            #pragma unroll
            for (int r = 0; r < 16; r++) Linv[r][c] = x[r];
        }
        __syncthreads();

        if (t > 0) {
            float s = 0.f;
            #pragma unroll
            for (int k = 0; k < 16; k++) s += Linv[i][k] * Mb[k][j];
            W[i][j] = s;
            __syncthreads();
            for (int sb = 0; sb < t; sb++) {
                float u = 0.f;
                #pragma unroll
                for (int k = 0; k < 16; k++) u += W[i][k] * prev[sb*256 + k*16 + j];
                cur[sb*256 + i*16 + j] = -u;
            }
        }
        cur[t*256 + i*16 + j] = Linv[i][j];
        __syncthreads();

        // write cov row t — float4 stores
        {
            float4* crow4 = (float4*)(cov + ((size_t)b*256 + t*16 + i) * 256);
            #pragma unroll
            for (int rep = 0; rep < 4; rep++) {
                int c0 = 4*j + 64*rep;
                int sb = c0 >> 4;
                int jj = c0 & 15;
                float4 v;
                if (sb <= t) {
                    const float* p = &cur[sb*256 + i*16 + jj];
                    v = make_float4(p[0], p[1], p[2], p[3]);
                } else {
                    v = make_float4(0.f, 0.f, 0.f, 0.f);
                }
                crow4[c0 >> 2] = v;
            }
        }

        // z: 16 j-lanes accumulate slices, 16-lane shfl reduce
        {
            float s = 0.f;
            for (int sb = 0; sb <= t; sb++)
                s += cur[sb*256 + i*16 + j] * epss[sb*16 + j];
            #pragma unroll
            for (int off = 8; off > 0; off >>= 1)
                s += __shfl_xor_sync(0xffffffffu, s, off, 16);
            if (j == 0)
                z[b*256 + t*16 + i] = mu[b*256 + t*16 + i] + s;
        }

        LinvP[i][j] = Linv[i][j];
        __syncthreads();

        float* tmp = prev; prev = cur; cur = tmp;
    }
}

// ---------------- launch ----------------
static inline int blocks_for(long total, int tpb) { return (int)((total + tpb - 1) / tpb); }

extern "C" void kernel_launch(void* const* d_in, const int* in_sizes, int n_in,
                              void* d_out, int out_size) {
    const float* x      = (const float*)d_in[0];
    const float* eps    = (const float*)d_in[1];
    const float* w1  = (const float*)d_in[2];   const float* b1  = (const float*)d_in[3];
    const float* w2  = (const float*)d_in[4];   const float* b2  = (const float*)d_in[5];
    const float* w3  = (const float*)d_in[6];   const float* b3  = (const float*)d_in[7];
    const float* w4  = (const float*)d_in[8];   const float* b4  = (const float*)d_in[9];
    const float* w5  = (const float*)d_in[10];  const float* b5  = (const float*)d_in[11];
    const float* fc_mu_w = (const float*)d_in[12]; const float* fc_mu_b = (const float*)d_in[13];
    const float* fc_D_w  = (const float*)d_in[14]; const float* fc_D_b  = (const float*)d_in[15];
    const float* fc_B_w  = (const float*)d_in[16]; const float* fc_B_b  = (const float*)d_in[17];
    const float* fc_dec_w = (const float*)d_in[18]; const float* fc_dec_b = (const float*)d_in[19];
    const float* wt5 = (const float*)d_in[20];  const float* bt5 = (const float*)d_in[21];
    const float* wt4 = (const float*)d_in[22];  const float* bt4 = (const float*)d_in[23];
    const float* wt3 = (const float*)d_in[24];  const float* bt3 = (const float*)d_in[25];
    const float* wt2 = (const float*)d_in[26];  const float* bt2 = (const float*)d_in[27];
    const float* wt1 = (const float*)d_in[28];  const float* bt1 = (const float*)d_in[29];

    float* out = (float*)d_out;
    float* o_xr  = out;
    float* o_mu  = out + MU_OFF;
    float* o_cov = out + COV_OFF;
    float* o_pm  = out + PM_OFF;

    float *h1,*h2,*h3,*h4,*h5,*Dv,*Bv,*zb,*hd,*d1,*d2,*d3,*d4;
    float *wp4,*wp3,*wp2,*w5p,*wp5g,*bt5e;
    cudaGetSymbolAddress((void**)&h1, g_h1);
    cudaGetSymbolAddress((void**)&h2, g_h2);
    cudaGetSymbolAddress((void**)&h3, g_h3);
    cudaGetSymbolAddress((void**)&h4, g_h4);
    cudaGetSymbolAddress((void**)&h5, g_h5);
    cudaGetSymbolAddress((void**)&Dv, g_Dv);
    cudaGetSymbolAddress((void**)&Bv, g_Bv);
    cudaGetSymbolAddress((void**)&zb, g_z);
    cudaGetSymbolAddress((void**)&hd, g_hd);
    cudaGetSymbolAddress((void**)&d1, g_d1);
    cudaGetSymbolAddress((void**)&d2, g_d2);
    cudaGetSymbolAddress((void**)&d3, g_d3);
    cudaGetSymbolAddress((void**)&d4, g_d4);
    cudaGetSymbolAddress((void**)&wp4, g_wp4);
    cudaGetSymbolAddress((void**)&wp3, g_wp3);
    cudaGetSymbolAddress((void**)&wp2, g_wp2);
    cudaGetSymbolAddress((void**)&w5p, g_w5p);
    cudaGetSymbolAddress((void**)&wp5g, g_wp5g);
    cudaGetSymbolAddress((void**)&bt5e, g_bt5e);

    const int TPB = 256;

    // all weight repacking in one launch
    pack_all<<<blocks_for(97536, TPB), TPB>>>(wt4, wt3, wt2, w5, wt5, bt5,
                                              wp4, wp3, wp2, w5p, wp5g, bt5e);

    // ---- encoder (R12 configs + hoisted staging) ----
    enc1_conv<<<1024, 256>>>(x, w1, b1, h1);
    enc_conv<32,16, 32, 2, 32, 256, 8, 4><<<1024, 256>>>(h1, w2, b2, h2);
    enc_conv<32, 8, 64, 2, 64, 256, 8, 8><<< 256, 256>>>(h2, w3, b3, h3);
    enc_conv<64, 4, 64, 2, 64, 128, 4, 8><<< 128, 256>>>(h3, w4, b4, h4);
    // enc5: pure GEMM [4096,256] @ [64,256]^T + ReLU
    { dim3 g(1, 64); gemm_bt64<1><<<g, 256>>>(h4, w5p, b5, h5, 4096, 64, 256); }

    // ---- merged FC heads ----
    { dim3 g(64, 2);
      gemm_heads<<<g, 256>>>(h5, fc_D_w, fc_D_b, Dv,
                                 fc_B_w, fc_B_b, Bv,
                                 fc_mu_w, fc_mu_b, o_mu); }

    // ---- Pm output ----
    build_pm4<<<blocks_for((long)BSZ*PT*64, TPB), TPB>>>(Dv, Bv, (float4*)o_pm);

    // ---- Cholesky + cov + z ----
    chol_cov_z<<<BSZ, 256>>>(Dv, Bv, o_mu, eps, o_cov, zb);

    // ---- decoder FC ----
    { dim3 g(16, 4); gemm_bt64<0><<<g, 256>>>(zb, fc_dec_w, fc_dec_b, hd, 256, 1024, 256); }

    // ---- dec1: pure GEMM [4096,64] @ [256,64]^T + ELU ----
    { dim3 g(4, 64); gemm_bt64<2><<<g, 256>>>(hd, wp5g, bt5e, d1, 4096, 256, 64); }

    // ---- decoder transposed convs (R12 configs + hoisted staging) ----
    { dim3 g(  64, 4); dec_convt<64, 2, 64, 64, 256, 8, 8, 0><<<g, 256>>>(d1, wp4, bt4, d2); }
    { dim3 g( 256, 4); dec_convt<64, 4, 32, 32, 256, 8, 4, 0><<<g, 256>>>(d2, wp3, bt3, d3); }
    { dim3 g(1024, 4); dec_convt<32, 8, 32, 32, 256, 8, 4, 0><<<g, 256>>>(d3, wp2, bt2, d4); }

    // ---- final layer ----
    dec_final<<<4096, 256>>>(d4, wt1, bt1, o_xr);
}

// round 17
// speedup vs baseline: 1.3759x; 1.3759x over previous
#include <cuda_runtime.h>
#include <math.h>

// ---------------- problem constants ----------------
#define BSZ 256
#define NT  4096        // BSZ*T images
#define PT  256
#define ALPHA_C 0.5f

#define XR_SZ   (NT*1024)
#define MU_OFF  XR_SZ
#define MU_SZ   (BSZ*PT)
#define COV_OFF (MU_OFF+MU_SZ)
#define COV_SZ  (BSZ*PT*PT)
#define PM_OFF  (COV_OFF+COV_SZ)

// ---------------- scratch ----------------
__device__ float g_h1[NT*32*16*16];
__device__ float g_h2[NT*32*8*8];
__device__ float g_h3[NT*64*4*4];
__device__ float g_h4[NT*64*2*2];
__device__ float g_h5[NT*64];
__device__ float g_Dv[BSZ*4096];
__device__ float g_Bv[BSZ*3840];
__device__ float g_z [BSZ*PT];
__device__ float g_hd[BSZ*1024];
__device__ float g_d1[NT*64*2*2];
__device__ float g_d2[NT*64*4*4];
__device__ float g_d3[NT*32*8*8];
__device__ float g_d4[NT*32*16*16];
__device__ float g_wp4[64*64*9];
__device__ float g_wp3[64*32*9];
__device__ float g_wp2[32*32*9];
__device__ float g_w5p[64*256];     // enc5 GEMM weights  [co][ci*4+iy*2+ix]
__device__ float g_wp5g[256*64];    // dec1 GEMM weights  [co*4+y*2+x][ci]
__device__ float g_bt5e[256];       // dec1 expanded bias

// =================================================================
// enc1 dedicated kernel: Conv(1->32, k3,s2,p1)+ReLU, 4 images/CTA.
// =================================================================
__global__ void __launch_bounds__(256)
enc1_conv(const float* __restrict__ x, const float* __restrict__ w,
          const float* __restrict__ bias, float* __restrict__ out) {
    int n0 = blockIdx.x * 4;
    __shared__ float si[4*1024];
    __shared__ float sw[288];
    __shared__ float sb[32];
    {
        const float4* gp = (const float4*)(x + (size_t)n0 * 1024);
        float4* sp = (float4*)si;
        #pragma unroll
        for (int l = 0; l < 4; l++) sp[threadIdx.x + l*256] = gp[threadIdx.x + l*256];
        for (int e = threadIdx.x; e < 288; e += 256) sw[e] = w[e];
        if (threadIdx.x < 32)  sb[threadIdx.x] = bias[threadIdx.x];
    }
    __syncthreads();
    int p = threadIdx.x;
    int y = p >> 4, xc = p & 15;

    float in9[4][9];
    #pragma unroll
    for (int q = 0; q < 4; q++) {
        #pragma unroll
        for (int ky = 0; ky < 3; ky++) {
            int iy = 2*y + ky - 1;
            #pragma unroll
            for (int kx = 0; kx < 3; kx++) {
                int ix = 2*xc + kx - 1;
                in9[q][ky*3+kx] = ((unsigned)iy < 32u && (unsigned)ix < 32u)
                                  ? si[q*1024 + iy*32 + ix] : 0.f;
            }
        }
    }
    for (int c = 0; c < 32; c++) {
        float wv[9];
        #pragma unroll
        for (int k = 0; k < 9; k++) wv[k] = sw[c*9 + k];
        float bb = sb[c];
        #pragma unroll
        for (int q = 0; q < 4; q++) {
            float s = bb;
            #pragma unroll
            for (int k = 0; k < 9; k++) s += in9[q][k] * wv[k];
            out[(size_t)(n0 + q)*8192 + c*256 + p] = fmaxf(s, 0.f);
        }
    }
}

// =================================================================
// Encoder conv (k3,s2,p1) + ReLU as implicit GEMM. (R12 baseline)
// =================================================================
template<int CIN,int HIN,int COUT,int CB,int BM,int BN,int TM,int TNW>
__global__ void __launch_bounds__((BM/TM)*(BN/TNW))
enc_conv(const float* __restrict__ in, const float* __restrict__ w,
         const float* __restrict__ bias, float* __restrict__ out) {
    const int THR = (BM/TM)*(BN/TNW);
    const int H  = HIN/2;
    const int H2 = H*H;
    const int BK = 9*CB;
    __shared__ float As[BK][BM];
    __shared__ float Bs[BK][BN+4];
    const int tid = threadIdx.x;
    const int px0 = blockIdx.x * BN;
    const int MT  = BM/TM;
    const int tidm = tid % MT, tidn = tid / MT;

    float acc[TM][TNW] = {};

    for (int c0 = 0; c0 < CIN; c0 += CB) {
        for (int e = tid; e < BK*BM; e += THR) {
            int k = e / BM, co = e % BM;
            int cl = k / 9, tap = k - 9*cl;
            As[k][co] = w[(co*CIN + c0 + cl)*9 + tap];
        }
        for (int e = tid; e < BK*BN; e += THR) {
            int k = e / BN, col = e % BN;
            int cl = k / 9, tap = k - 9*cl;
            int ky = tap/3, kx = tap - 3*(tap/3);
            int px = px0 + col;
            int n   = px / H2;
            int rem = px - n*H2;
            int y = rem / H, x = rem - (rem/H)*H;
            int iy = 2*y + ky - 1, ix = 2*x + kx - 1;
            float v = 0.f;
            if ((unsigned)iy < (unsigned)HIN && (unsigned)ix < (unsigned)HIN)
                v = in[(((size_t)n*CIN + c0 + cl)*HIN + iy)*HIN + ix];
            Bs[k][col] = v;
        }
        __syncthreads();
        #pragma unroll
        for (int k = 0; k < BK; k++) {
            float a[TM], b[TNW];
            #pragma unroll
            for (int r = 0; r < TM; r++) a[r] = As[k][tidm*TM + r];
            #pragma unroll
            for (int c = 0; c < TNW; c++) b[c] = Bs[k][tidn*TNW + c];
            #pragma unroll
            for (int r = 0; r < TM; r++)
                #pragma unroll
                for (int c = 0; c < TNW; c++)
                    acc[r][c] += a[r] * b[c];
        }
        __syncthreads();
    }
    #pragma unroll
    for (int r = 0; r < TM; r++) {
        int co = tidm*TM + r;
        float bb = bias[co];
        #pragma unroll
        for (int c = 0; c < TNW; c++) {
            int px = px0 + tidn*TNW + c;
            int n = px / H2, rem = px - (px/H2)*H2;
            out[((size_t)n*COUT + co)*H2 + rem] = fmaxf(acc[r][c] + bb, 0.f);
        }
    }
}

// =================================================================
// Encoder conv with SMEM-hoisted staging offsets (enc3 experiment).
// Offset table lives in shared memory: no register pressure, fill/use
// loops share the e = tid + s*THR mapping so no extra sync needed.
// =================================================================
template<int CIN,int HIN,int COUT,int CB,int BM,int BN,int TM,int TNW>
__global__ void __launch_bounds__((BM/TM)*(BN/TNW))
enc_conv_h(const float* __restrict__ in, const float* __restrict__ w,
           const float* __restrict__ bias, float* __restrict__ out) {
    const int THR = (BM/TM)*(BN/TNW);
    const int H  = HIN/2;
    const int H2 = H*H;
    const int BK = 9*CB;
    __shared__ float As[BK][BM];
    __shared__ float Bs[BK][BN+4];
    __shared__ int   sboff[BK*BN];
    const int tid = threadIdx.x;
    const int px0 = blockIdx.x * BN;
    const int MT  = BM/TM;
    const int tidm = tid % MT, tidn = tid / MT;

    // fill offset table once (c0 = 0 base; -1 = padding)
    for (int e = tid; e < BK*BN; e += THR) {
        int k = e / BN, col = e % BN;
        int cl = k / 9, tap = k - 9*cl;
        int ky = tap/3, kx = tap - 3*(tap/3);
        int px = px0 + col;
        int n   = px / H2;
        int rem = px - n*H2;
        int y = rem / H, x = rem - (rem/H)*H;
        int iy = 2*y + ky - 1, ix = 2*x + kx - 1;
        bool ok = ((unsigned)iy < (unsigned)HIN) && ((unsigned)ix < (unsigned)HIN);
        sboff[e] = ok ? (((n*CIN + cl)*HIN + iy)*HIN + ix) : -1;
    }

    float acc[TM][TNW] = {};
    int coff = 0;

    for (int c0 = 0; c0 < CIN; c0 += CB, coff += CB*HIN*HIN) {
        for (int e = tid; e < BK*BM; e += THR) {
            int k = e / BM, co = e % BM;
            int cl = k / 9, tap = k - 9*cl;
            As[k][co] = w[(co*CIN + c0 + cl)*9 + tap];
        }
        for (int e = tid; e < BK*BN; e += THR) {
            int k = e / BN, col = e % BN;
            int off = sboff[e];                 // same thread wrote it
            float v = 0.f;
            if (off >= 0) v = in[(size_t)off + coff];
            Bs[k][col] = v;
        }
        __syncthreads();
        #pragma unroll
        for (int k = 0; k < BK; k++) {
            float a[TM], b[TNW];
            #pragma unroll
            for (int r = 0; r < TM; r++) a[r] = As[k][tidm*TM + r];
            #pragma unroll
            for (int c = 0; c < TNW; c++) b[c] = Bs[k][tidn*TNW + c];
            #pragma unroll
            for (int r = 0; r < TM; r++)
                #pragma unroll
                for (int c = 0; c < TNW; c++)
                    acc[r][c] += a[r] * b[c];
        }
        __syncthreads();
    }
    #pragma unroll
    for (int r = 0; r < TM; r++) {
        int co = tidm*TM + r;
        float bb = bias[co];
        #pragma unroll
        for (int c = 0; c < TNW; c++) {
            int px = px0 + tidn*TNW + c;
            int n = px / H2, rem = px - (px/H2)*H2;
            out[((size_t)n*COUT + co)*H2 + rem] = fmaxf(acc[r][c] + bb, 0.f);
        }
    }
}

// =================================================================
// Weight packing
// =================================================================
__device__ __forceinline__ void pack_one(const float* __restrict__ w,
                                         float* __restrict__ wp,
                                         int CIN, int COUT, int idx) {
    int kx = idx % 3; int r = idx / 3;
    int ky = r % 3;   r /= 3;
    int co = r % COUT; int ci = r / COUT;
    int py = (ky != 1), px = (kx != 1);
    int p = py*2 + px;
    int ty = (ky == 2) ? 1 : 0;
    int tx = (kx == 2) ? 1 : 0;
    int ntx = px ? 2 : 1;
    int ntaps = (py ? 2 : 1) * ntx;
    int K = CIN * ntaps;
    const int cum[4] = {0, 1, 3, 5};
    int off = COUT*CIN*cum[p];
    wp[off + co*K + ci*ntaps + ty*ntx + tx] = w[((ci*COUT + co)*3 + ky)*3 + kx];
}

__global__ void pack_all(const float* __restrict__ wt4, const float* __restrict__ wt3,
                         const float* __restrict__ wt2,
                         const float* __restrict__ w5, const float* __restrict__ wt5,
                         const float* __restrict__ bt5,
                         float* wp4, float* wp3, float* wp2,
                         float* w5p, float* wp5g, float* bt5e) {
    int idx = blockIdx.x * blockDim.x + threadIdx.x;
    if      (idx < 36864)  pack_one(wt4, wp4, 64, 64, idx);
    else if (idx < 55296)  pack_one(wt3, wp3, 64, 32, idx - 36864);
    else if (idx < 64512)  pack_one(wt2, wp2, 32, 32, idx - 55296);
    else if (idx < 80896) {
        int e = idx - 64512;
        int ix = e & 1, iy = (e >> 1) & 1, ci = (e >> 2) & 63, co = e >> 8;
        w5p[co*256 + ci*4 + iy*2 + ix] = w5[((co*64 + ci)*3 + iy+1)*3 + ix+1];
    }
    else if (idx < 97280) {
        int e = idx - 80896;
        int ci = e & 63, yx = (e >> 6) & 3, co = e >> 8;
        int y = yx >> 1, x = yx & 1;
        wp5g[(co*4 + yx)*64 + ci] = wt5[((ci*64 + co)*3 + y+1)*3 + x+1];
    }
    else if (idx < 97536) {
        int e = idx - 97280;
        bt5e[e] = bt5[e >> 2];
    }
}

// =================================================================
// Decoder transposed conv (parity decomposition), implicit GEMM. (R12)
// =================================================================
template<int CIN,int HI,int COUT,int BM,int BN,int TM,int TNW,int ACT>
__global__ void __launch_bounds__((BM/TM)*(BN/TNW))
dec_convt(const float* __restrict__ in, const float* __restrict__ wp,
          const float* __restrict__ bias, float* __restrict__ out) {
    const int THR = (BM/TM)*(BN/TNW);
    const int HO  = 2*HI;
    const int HI2 = HI*HI;
    const int BK = 16;
    __shared__ float As[BK][BM];
    __shared__ float Bs[BK][BN+4];
    const int tid = threadIdx.x;
    const int par = blockIdx.y;
    const int py = par >> 1, pxp = par & 1;
    const int sh = py + pxp;
    const int ntaps = 1 << sh;
    const int ntxm1 = pxp;
    const int K = CIN << sh;
    const int cum[4] = {0, 1, 3, 5};
    const float* wq = wp + (size_t)COUT*CIN*cum[par];

    const int pxl0 = blockIdx.x * BN;
    const int MT = BM/TM;
    const int tidm = tid % MT, tidn = tid / MT;

    float acc[TM][TNW] = {};

    for (int k0 = 0; k0 < K; k0 += BK) {
        for (int e = tid; e < BK*BM; e += THR) {
            int k = e / BM, co = e % BM;
            As[k][co] = wq[co*K + k0 + k];
        }
        for (int e = tid; e < BK*BN; e += THR) {
            int kk = e / BN, col = e % BN;
            int k = k0 + kk;
            int ci = k >> sh;
            int t  = k & (ntaps - 1);
            int ty = t >> pxp;
            int tx = t & ntxm1;
            int dy = (py && ty == 0) ? 1 : 0;
            int dx = (pxp && tx == 0) ? 1 : 0;
            int pxl = pxl0 + col;
            int n   = pxl / HI2;
            int rem = pxl - n*HI2;
            int yi = rem / HI, xi = rem - (rem/HI)*HI;
            int iy = yi + dy, ix = xi + dx;
            float v = 0.f;
            if (iy < HI && ix < HI)
                v = in[(((size_t)n*CIN + ci)*HI + iy)*HI + ix];
            Bs[kk][col] = v;
        }
        __syncthreads();
        #pragma unroll
        for (int k = 0; k < BK; k++) {
            float a[TM], b[TNW];
            #pragma unroll
            for (int r = 0; r < TM; r++) a[r] = As[k][tidm*TM + r];
            #pragma unroll
            for (int c = 0; c < TNW; c++) b[c] = Bs[k][tidn*TNW + c];
            #pragma unroll
            for (int r = 0; r < TM; r++)
                #pragma unroll
                for (int c = 0; c < TNW; c++)
                    acc[r][c] += a[r] * b[c];
        }
        __syncthreads();
    }
    #pragma unroll
    for (int r = 0; r < TM; r++) {
        int co = tidm*TM + r;
        float bb = bias[co];
        #pragma unroll
        for (int c = 0; c < TNW; c++) {
            int pxl = pxl0 + tidn*TNW + c;
            int n   = pxl / HI2;
            int rem = pxl - n*HI2;
            int yi = rem / HI, xi = rem - (rem/HI)*HI;
            float s = acc[r][c] + bb;
            float o;
            if (ACT) o = 1.f / (1.f + expf(-s));
            else     o = (s > 0.f) ? s : expm1f(s);
            out[(((size_t)n*COUT + co)*HO + 2*yi + py)*HO + 2*xi + pxp] = o;
        }
    }
}

// =================================================================
// Final decoder layer (Cout=1) + sigmoid: one CTA per image.
// =================================================================
__global__ void __launch_bounds__(256)
dec_final(const float* __restrict__ in, const float* __restrict__ w,
          const float* __restrict__ bias, float* __restrict__ out) {
    int n = blockIdx.x;
    __shared__ float si[32*256];
    __shared__ float sw[288];
    const float4* gp = (const float4*)(in + (size_t)n * 8192);
    float4* sp = (float4*)si;
    for (int e = threadIdx.x; e < 2048; e += 256) sp[e] = gp[e];
    for (int e = threadIdx.x; e < 288; e += 256)  sw[e] = w[e];
    __syncthreads();
    float b0 = bias[0];
    #pragma unroll
    for (int p = 0; p < 4; p++) {
        int px = threadIdx.x + p*256;
        int y = px >> 5, x = px & 31;
        float s = b0;
        #pragma unroll
        for (int ky = 0; ky < 3; ky++) {
            int ty = y + 1 - ky;
            if (ty < 0 || (ty & 1)) continue;
            int iy = ty >> 1;
            if (iy >= 16) continue;
            #pragma unroll
            for (int kx = 0; kx < 3; kx++) {
                int tx = x + 1 - kx;
                if (tx < 0 || (tx & 1)) continue;
                int ix = tx >> 1;
                if (ix >= 16) continue;
                const float* sic = si + iy*16 + ix;
                const float* swc = sw + ky*3 + kx;
                #pragma unroll 8
                for (int ci = 0; ci < 32; ci++)
                    s += sic[ci*256] * swc[ci*9];
            }
        }
        out[(size_t)n*1024 + px] = 1.f / (1.f + expf(-s));
    }
}

// =================================================================
// Merged FC-heads GEMM, 8x8 microtile, float4 staging.
// =================================================================
__global__ void __launch_bounds__(256)
gemm_heads(const float* __restrict__ A,
           const float* __restrict__ wD, const float* __restrict__ bD, float* __restrict__ oD,
           const float* __restrict__ wB, const float* __restrict__ bB, float* __restrict__ oB,
           const float* __restrict__ wM, const float* __restrict__ bM, float* __restrict__ oM) {
    const int K = 1024;
    __shared__ float As[16][132];
    __shared__ float Bs[16][132];
    int tid = threadIdx.x;
    int tidm = tid & 15, tidn = tid >> 4;
    int m0 = blockIdx.y * 128;
    int ng = blockIdx.x * 128;

    const float* W; const float* bias; float* C; int Nld; int n0;
    if (ng < 4096)      { W = wD; bias = bD; C = oD; Nld = 4096; n0 = ng; }
    else if (ng < 7936) { W = wB; bias = bB; C = oB; Nld = 3840; n0 = ng - 4096; }
    else                { W = wM; bias = bM; C = oM; Nld = 256;  n0 = ng - 7936; }

    float acc[8][8] = {};
    for (int k0 = 0; k0 < K; k0 += 16) {
        #pragma unroll
        for (int l = 0; l < 2; l++) {
            int q = tid + l*256;
            int row = q >> 2, kq = q & 3;
            float4 v = *(const float4*)&A[(size_t)(m0 + row)*K + k0 + kq*4];
            As[kq*4+0][row] = v.x; As[kq*4+1][row] = v.y;
            As[kq*4+2][row] = v.z; As[kq*4+3][row] = v.w;
        }
        #pragma unroll
        for (int l = 0; l < 2; l++) {
            int q = tid + l*256;
            int row = q >> 2, kq = q & 3;
            float4 v = *(const float4*)&W[(size_t)(n0 + row)*K + k0 + kq*4];
            Bs[kq*4+0][row] = v.x; Bs[kq*4+1][row] = v.y;
            Bs[kq*4+2][row] = v.z; Bs[kq*4+3][row] = v.w;
        }
        __syncthreads();
        #pragma unroll
        for (int k = 0; k < 16; k++) {
            float a[8], b[8];
            #pragma unroll
            for (int r = 0; r < 8; r++) a[r] = As[k][tidm*8 + r];
            #pragma unroll
            for (int c = 0; c < 8; c++) b[c] = Bs[k][tidn*8 + c];
            #pragma unroll
            for (int r = 0; r < 8; r++)
                #pragma unroll
                for (int c = 0; c < 8; c++)
                    acc[r][c] += a[r] * b[c];
        }
        __syncthreads();
    }
    #pragma unroll
    for (int r = 0; r < 8; r++) {
        int m = m0 + tidm*8 + r;
        #pragma unroll
        for (int c = 0; c < 8; c++) {
            int n = n0 + tidn*8 + c;
            C[(size_t)m*Nld + n] = acc[r][c] + bias[n];
        }
    }
}

// ---------------- generic GEMM + activation: C = A@B^T + bias ----------------
template<int ACT>
__global__ void gemm_bt64(const float* __restrict__ A, const float* __restrict__ Bm,
                          const float* __restrict__ bias, float* __restrict__ C,
                          int M, int N, int K) {
    __shared__ float As[64][17];
    __shared__ float Bs[64][17];
    int tid = threadIdx.x;
    int tx = tid & 15, ty = tid >> 4;
    int m0 = blockIdx.y * 64, n0 = blockIdx.x * 64;

    float acc[4][4] = {};
    for (int k0 = 0; k0 < K; k0 += 16) {
        #pragma unroll
        for (int l = 0; l < 4; l++) {
            int e = tid + l * 256;
            int mm = e >> 4, kk = e & 15;
            As[mm][kk] = A[(size_t)(m0 + mm) * K + k0 + kk];
            Bs[mm][kk] = Bm[(size_t)(n0 + mm) * K + k0 + kk];
        }
        __syncthreads();
        #pragma unroll
        for (int k = 0; k < 16; k++) {
            float a[4], b[4];
            #pragma unroll
            for (int r = 0; r < 4; r++) a[r] = As[ty*4 + r][k];
            #pragma unroll
            for (int c = 0; c < 4; c++) b[c] = Bs[tx*4 + c][k];
            #pragma unroll
            for (int r = 0; r < 4; r++)
                #pragma unroll
                for (int c = 0; c < 4; c++)
                    acc[r][c] += a[r] * b[c];
        }
        __syncthreads();
    }
    #pragma unroll
    for (int r = 0; r < 4; r++)
        #pragma unroll
        for (int c = 0; c < 4; c++) {
            float v = acc[r][c] + bias[n0 + tx*4 + c];
            if (ACT == 1) v = fmaxf(v, 0.f);
            if (ACT == 2) v = (v > 0.f) ? v : expm1f(v);
            C[(size_t)(m0 + ty*4 + r) * N + n0 + tx*4 + c] = v;
        }
}

// ---------------- Pm builder — float4 stores ----------------
__global__ void build_pm4(const float* __restrict__ Dv, const float* __restrict__ Bv,
                          float4* __restrict__ Pm) {
    size_t idx = (size_t)blockIdx.x * blockDim.x + threadIdx.x;
    size_t total = (size_t)BSZ * PT * 64;
    if (idx >= total) return;
    int c4 = idx & 63;
    int r  = (idx >> 6) & 255;
    int b  = idx >> 14;
    int t = r >> 4, i = r & 15;
    int s = c4 >> 2, j0 = (c4 & 3) * 4;
    float4 v = {0.f, 0.f, 0.f, 0.f};
    if (t == s) {
        v = *(const float4*)(Dv + b*4096 + t*256 + i*16 + j0);
        if (i >= j0 && i < j0+4) { (&v.x)[i - j0] += ALPHA_C; }
    } else if (t == s + 1) {
        v = *(const float4*)(Bv + b*3840 + s*256 + i*16 + j0);
    } else if (s == t + 1) {
        const float* bp = Bv + b*3840 + t*256 + i;
        v.x = bp[(j0+0)*16]; v.y = bp[(j0+1)*16];
        v.z = bp[(j0+2)*16]; v.w = bp[(j0+3)*16];
    }
    Pm[idx] = v;
}

// ---------------- block-tridiagonal Cholesky + L^{-1} + z ----------------
__global__ void chol_cov_z(const float* __restrict__ Dv, const float* __restrict__ Bv,
                           const float* __restrict__ mu, const float* __restrict__ eps,
                           float* __restrict__ cov, float* __restrict__ z) {
    int b = blockIdx.x;
    int tid = threadIdx.x;
    int i = tid >> 4, j = tid & 15;

    __shared__ float A[16][16];
    __shared__ float Linv[16][16];
    __shared__ float LinvP[16][16];
    __shared__ float Mb[16][16];
    __shared__ float W[16][16];
    __shared__ float rowbuf[2][16*256];
    __shared__ float epss[256];

    epss[tid] = eps[b*256 + tid];

    float* prev = rowbuf[0];
    float* cur  = rowbuf[1];

    for (int t = 0; t < 16; t++) {
        const float* Dp = Dv + b*4096 + t*256;
        float a = 0.5f * (Dp[i*16 + j] + Dp[j*16 + i]);   // symmetrize_input=True
        if (i == j) a += ALPHA_C;
        __syncthreads();
        A[i][j] = a;
        __syncthreads();

        if (t > 0) {
            const float* Bp = Bv + b*3840 + (t-1)*256;
            float s = 0.f;
            #pragma unroll
            for (int k = 0; k < 16; k++) s += Bp[i*16 + k] * LinvP[j][k];
            Mb[i][j] = s;
            __syncthreads();
            float u = 0.f;
            #pragma unroll
            for (int k = 0; k < 16; k++) u += Mb[i][k] * Mb[j][k];
            A[i][j] -= u;
            __syncthreads();
        }

        // Cholesky: 2 barriers per column
        for (int k = 0; k < 16; k++) {
            float aik = A[i][k], ajk = A[j][k], akk = A[k][k];
            __syncthreads();
            if (j == k && i >= k)      A[i][k] = aik * rsqrtf(akk);
            else if (j > k && j <= i)  A[i][j] -= aik * ajk / akk;
            __syncthreads();
        }

        // Linv = A_lower^{-1} : 16 threads, fully unrolled
        if (tid < 16) {
            int c = tid;
            float x[16];
            #pragma unroll
            for (int r = 0; r < 16; r++) {
                float s = 0.f;
                #pragma unroll
                for (int k = 0; k < 16; k++)
                    if (k < r) s += A[r][k] * x[k];
                float v;
                if (r == c)      v = 1.f / A[r][r];
                else if (r < c)  v = 0.f;
                else             v = -s / A[r][r];
                x[r] = v;
            }
            #pragma unroll
            for (int r = 0; r < 16; r++) Linv[r][c] = x[r];
        }
        __syncthreads();

        if (t > 0) {
            float s = 0.f;
            #pragma unroll
            for (int k = 0; k < 16; k++) s += Linv[i][k] * Mb[k][j];
            W[i][j] = s;
            __syncthreads();
            for (int sb = 0; sb < t; sb++) {
                float u = 0.f;
                #pragma unroll
                for (int k = 0; k < 16; k++) u += W[i][k] * prev[sb*256 + k*16 + j];
                cur[sb*256 + i*16 + j] = -u;
            }
        }
        cur[t*256 + i*16 + j] = Linv[i][j];
        __syncthreads();

        // write cov row t
        float* crow = cov + ((size_t)b*256 + t*16 + i) * 256;
        for (int sb = 0; sb < 16; sb++)
            crow[sb*16 + j] = (sb <= t) ? cur[sb*256 + i*16 + j] : 0.f;

        // z: 16 j-lanes accumulate slices, 16-lane shfl reduce
        {
            float s = 0.f;
            for (int sb = 0; sb <= t; sb++)
                s += cur[sb*256 + i*16 + j] * epss[sb*16 + j];
            #pragma unroll
            for (int off = 8; off > 0; off >>= 1)
                s += __shfl_xor_sync(0xffffffffu, s, off, 16);
            if (j == 0)
                z[b*256 + t*16 + i] = mu[b*256 + t*16 + i] + s;
        }

        LinvP[i][j] = Linv[i][j];
        __syncthreads();

        float* tmp = prev; prev = cur; cur = tmp;
    }
}

// ---------------- launch ----------------
static inline int blocks_for(long total, int tpb) { return (int)((total + tpb - 1) / tpb); }

extern "C" void kernel_launch(void* const* d_in, const int* in_sizes, int n_in,
                              void* d_out, int out_size) {
    const float* x      = (const float*)d_in[0];
    const float* eps    = (const float*)d_in[1];
    const float* w1  = (const float*)d_in[2];   const float* b1  = (const float*)d_in[3];
    const float* w2  = (const float*)d_in[4];   const float* b2  = (const float*)d_in[5];
    const float* w3  = (const float*)d_in[6];   const float* b3  = (const float*)d_in[7];
    const float* w4  = (const float*)d_in[8];   const float* b4  = (const float*)d_in[9];
    const float* w5  = (const float*)d_in[10];  const float* b5  = (const float*)d_in[11];
    const float* fc_mu_w = (const float*)d_in[12]; const float* fc_mu_b = (const float*)d_in[13];
    const float* fc_D_w  = (const float*)d_in[14]; const float* fc_D_b  = (const float*)d_in[15];
    const float* fc_B_w  = (const float*)d_in[16]; const float* fc_B_b  = (const float*)d_in[17];
    const float* fc_dec_w = (const float*)d_in[18]; const float* fc_dec_b = (const float*)d_in[19];
    const float* wt5 = (const float*)d_in[20];  const float* bt5 = (const float*)d_in[21];
    const float* wt4 = (const float*)d_in[22];  const float* bt4 = (const float*)d_in[23];
    const float* wt3 = (const float*)d_in[24];  const float* bt3 = (const float*)d_in[25];
    const float* wt2 = (const float*)d_in[26];  const float* bt2 = (const float*)d_in[27];
    const float* wt1 = (const float*)d_in[28];  const float* bt1 = (const float*)d_in[29];

    float* out = (float*)d_out;
    float* o_xr  = out;
    float* o_mu  = out + MU_OFF;
    float* o_cov = out + COV_OFF;
    float* o_pm  = out + PM_OFF;

    float *h1,*h2,*h3,*h4,*h5,*Dv,*Bv,*zb,*hd,*d1,*d2,*d3,*d4;
    float *wp4,*wp3,*wp2,*w5p,*wp5g,*bt5e;
    cudaGetSymbolAddress((void**)&h1, g_h1);
    cudaGetSymbolAddress((void**)&h2, g_h2);
    cudaGetSymbolAddress((void**)&h3, g_h3);
    cudaGetSymbolAddress((void**)&h4, g_h4);
    cudaGetSymbolAddress((void**)&h5, g_h5);
    cudaGetSymbolAddress((void**)&Dv, g_Dv);
    cudaGetSymbolAddress((void**)&Bv, g_Bv);
    cudaGetSymbolAddress((void**)&zb, g_z);
    cudaGetSymbolAddress((void**)&hd, g_hd);
    cudaGetSymbolAddress((void**)&d1, g_d1);
    cudaGetSymbolAddress((void**)&d2, g_d2);
    cudaGetSymbolAddress((void**)&d3, g_d3);
    cudaGetSymbolAddress((void**)&d4, g_d4);
    cudaGetSymbolAddress((void**)&wp4, g_wp4);
    cudaGetSymbolAddress((void**)&wp3, g_wp3);
    cudaGetSymbolAddress((void**)&wp2, g_wp2);
    cudaGetSymbolAddress((void**)&w5p, g_w5p);
    cudaGetSymbolAddress((void**)&wp5g, g_wp5g);
    cudaGetSymbolAddress((void**)&bt5e, g_bt5e);

    const int TPB = 256;

    // all weight repacking in one launch
    pack_all<<<blocks_for(97536, TPB), TPB>>>(wt4, wt3, wt2, w5, wt5, bt5,
                                              wp4, wp3, wp2, w5p, wp5g, bt5e);

    // ---- encoder (R12 configs; enc3 = SMEM-hoisted experiment) ----
    enc1_conv<<<1024, 256>>>(x, w1, b1, h1);
    enc_conv  <32,16, 32, 2, 32, 256, 8, 4><<<1024, 256>>>(h1, w2, b2, h2);
    enc_conv_h<32, 8, 64, 2, 64, 256, 8, 8><<< 256, 256>>>(h2, w3, b3, h3);
    enc_conv  <64, 4, 64, 2, 64, 128, 4, 8><<< 128, 256>>>(h3, w4, b4, h4);
    // enc5: pure GEMM [4096,256] @ [64,256]^T + ReLU
    { dim3 g(1, 64); gemm_bt64<1><<<g, 256>>>(h4, w5p, b5, h5, 4096, 64, 256); }

    // ---- merged FC heads ----
    { dim3 g(64, 2);
      gemm_heads<<<g, 256>>>(h5, fc_D_w, fc_D_b, Dv,
                                 fc_B_w, fc_B_b, Bv,
                                 fc_mu_w, fc_mu_b, o_mu); }

    // ---- Pm output ----
    build_pm4<<<blocks_for((long)BSZ*PT*64, TPB), TPB>>>(Dv, Bv, (float4*)o_pm);

    // ---- Cholesky + cov + z ----
    chol_cov_z<<<BSZ, 256>>>(Dv, Bv, o_mu, eps, o_cov, zb);

    // ---- decoder FC ----
    { dim3 g(16, 4); gemm_bt64<0><<<g, 256>>>(zb, fc_dec_w, fc_dec_b, hd, 256, 1024, 256); }

    // ---- dec1: pure GEMM [4096,64] @ [256,64]^T + ELU ----
    { dim3 g(4, 64); gemm_bt64<2><<<g, 256>>>(hd, wp5g, bt5e, d1, 4096, 256, 64); }

    // ---- decoder transposed convs (R12 configs) ----
    { dim3 g(  64, 4); dec_convt<64, 2, 64, 64, 256, 8, 8, 0><<<g, 256>>>(d1, wp4, bt4, d2); }
    { dim3 g( 256, 4); dec_convt<64, 4, 32, 32, 256, 8, 4, 0><<<g, 256>>>(d2, wp3, bt3, d3); }
    { dim3 g(1024, 4); dec_convt<32, 8, 32, 32, 256, 8, 4, 0><<<g, 256>>>(d3, wp2, bt2, d4); }

    // ---- final layer ----
    dec_final<<<4096, 256>>>(d4, wt1, bt1, o_xr);
}